// round 13
// baseline (speedup 1.0000x reference)
#include <cuda_runtime.h>
#include <math_constants.h>

#define B_      64
#define T_      2048
#define RNN_    1024
#define EMB_    512
#define ATT_    128
#define NF_     32
#define KS_     31
#define PAD_    15
#define TILE_   128

// scratch (no allocs allowed)
__device__ float g_pq[B_ * ATT_];       // processed query [B,128]
__device__ float g_energy[B_ * T_];     // pre-softmax energies [B,T]
__device__ float g_prob[B_ * T_];       // normalized attention weights [B,T]

// ---------------------------------------------------------------------------
// K1: g_pq[b,a] = sum_r query[b,r] * W_query[a,r]
// grid 512: block = (b, chunk of 16 a). q staged in smem; each Wq row read
// exactly once chip-wide. 8 warps x 2 outputs per warp.
// ---------------------------------------------------------------------------
__global__ __launch_bounds__(256) void k_query(const float* __restrict__ q,
                                               const float* __restrict__ Wq) {
    const int b = blockIdx.x >> 3;
    const int ch = blockIdx.x & 7;
    const int tid = threadIdx.x;
    const int w = tid >> 5, lane = tid & 31;
    __shared__ float4 s_q[256];
    s_q[tid] = reinterpret_cast<const float4*>(q + (size_t)b * RNN_)[tid];
    __syncthreads();
    const int a0 = ch * 16 + w * 2;
    const float4* w0 = reinterpret_cast<const float4*>(Wq + (size_t)a0 * RNN_);
    const float4* w1 = w0 + 256;
    float acc0 = 0.f, acc1 = 0.f;
#pragma unroll
    for (int j = 0; j < 8; j++) {
        float4 x = s_q[j * 32 + lane];
        float4 u = w0[j * 32 + lane];
        float4 v = w1[j * 32 + lane];
        acc0 += u.x * x.x + u.y * x.y + u.z * x.z + u.w * x.w;
        acc1 += v.x * x.x + v.y * x.y + v.z * x.z + v.w * x.w;
    }
#pragma unroll
    for (int off = 16; off; off >>= 1) {
        acc0 += __shfl_xor_sync(0xffffffffu, acc0, off);
        acc1 += __shfl_xor_sync(0xffffffffu, acc1, off);
    }
    if (lane == 0) {
        g_pq[b * ATT_ + a0] = acc0;
        g_pq[b * ATT_ + a0 + 1] = acc1;
    }
}

// ---------------------------------------------------------------------------
// K2: energies. grid (16, 64), 128 threads; thread = local time index t.
// conv results loc[32] live in registers; loop over a with W_loc broadcast
// from smem and pm staged in 32-a chunks. No cross-thread reduction at all.
// ---------------------------------------------------------------------------
__global__ __launch_bounds__(128, 5) void k_energy(const float* __restrict__ pm,
                                                   const float* __restrict__ cat,
                                                   const int* __restrict__ mask,
                                                   const float* __restrict__ cw,
                                                   const float* __restrict__ Wl,
                                                   const float* __restrict__ vw) {
    const int b = blockIdx.y;
    const int t0 = blockIdx.x * TILE_;
    const int tid = threadIdx.x;

    __shared__ float s_cat[2][TILE_ + 32];                  // 1.25 KB
    __shared__ __align__(16) float s_cw[2][NF_][32];        // 8 KB [c][f][k]
    __shared__ float4 s_wl[ATT_][8];                        // 16 KB Wl[a][f/4]
    __shared__ float s_pq[ATT_];
    __shared__ float s_v[ATT_];
    __shared__ float s_pm[TILE_ * 33];                      // 16.9 KB (pad 33)

    // stage conv input window (zero pad at boundaries + tail)
#pragma unroll
    for (int c = 0; c < 2; c++) {
        for (int i = tid; i < TILE_ + 32; i += 128) {
            int g = t0 - PAD_ + i;
            float v = 0.f;
            if (i < TILE_ + 2 * PAD_ && g >= 0 && g < T_)
                v = cat[((size_t)(b * 2 + c)) * T_ + g];
            s_cat[c][i] = v;
        }
    }
    // conv weights transposed [c][f][k], k padded to 32 with 0
    for (int i = tid; i < 2 * NF_ * 32; i += 128) {
        int c = i >> 10;
        int f = (i >> 5) & 31;
        int k = i & 31;
        s_cw[c][f][k] = (k < KS_) ? cw[(f * 2 + c) * KS_ + k] : 0.f;
    }
    // W_loc [128 a][32 f] -> smem as float4
    for (int i = tid; i < ATT_ * 8; i += 128)
        reinterpret_cast<float4*>(s_wl)[i] = reinterpret_cast<const float4*>(Wl)[i];
    s_pq[tid] = g_pq[b * ATT_ + tid];
    s_v[tid] = vw[tid];
    __syncthreads();

    // ---- conv: loc[0..31] in registers, one channel at a time ----
    float loc[NF_];
#pragma unroll
    for (int i = 0; i < NF_; i++) loc[i] = 0.f;
#pragma unroll
    for (int c = 0; c < 2; c++) {
        float xr[32];
#pragma unroll
        for (int i = 0; i < 32; i++) xr[i] = s_cat[c][tid + i];
#pragma unroll
        for (int j = 0; j < NF_; j++) {
            float a = 0.f;
#pragma unroll
            for (int kk = 0; kk < 8; kk++) {
                float4 w = *reinterpret_cast<const float4*>(&s_cw[c][j][4 * kk]);
                a += w.x * xr[4 * kk] + w.y * xr[4 * kk + 1] +
                     w.z * xr[4 * kk + 2] + w.w * xr[4 * kk + 3];
            }
            loc[j] += a;
        }
    }

    // ---- energies: e[t] = sum_a v[a] * tanh(pq[a] + pm[t,a] + Wl[a,:].loc) ----
    float e = 0.f;
#pragma unroll
    for (int chv = 0; chv < 4; chv++) {
        // stage pm tile [128 t][32 a] into padded smem.
        // NOTE: stride 33 floats => odd-t rows are NOT 16B-aligned, so the
        // store side MUST be scalar (STS.128 here traps: misaligned address).
        // Scalar store banks: (33t+4a4+k)%32 = (t+4a4+k)%32 -> conflict-free.
        __syncthreads();
#pragma unroll
        for (int r = 0; r < 8; r++) {
            int i = r * 128 + tid;          // 0..1023 float4s
            int t = i >> 3, a4 = i & 7;
            float4 v4 = *reinterpret_cast<const float4*>(
                pm + ((size_t)(b * T_) + t0 + t) * ATT_ + chv * 32 + a4 * 4);
            float* dst = &s_pm[t * 33 + a4 * 4];
            dst[0] = v4.x; dst[1] = v4.y; dst[2] = v4.z; dst[3] = v4.w;
        }
        __syncthreads();
#pragma unroll 4
        for (int aa = 0; aa < 32; aa++) {
            int a = chv * 32 + aa;
            float z = s_pq[a] + s_pm[tid * 33 + aa];
#pragma unroll
            for (int j = 0; j < 8; j++) {
                float4 w = s_wl[a][j];
                z += w.x * loc[4 * j] + w.y * loc[4 * j + 1] +
                     w.z * loc[4 * j + 2] + w.w * loc[4 * j + 3];
            }
            float th;
            asm("tanh.approx.f32 %0, %1;" : "=f"(th) : "f"(z));
            e += s_v[a] * th;
        }
    }
    const int gt = b * T_ + t0 + tid;
    if (mask[gt] != 0) e = -CUDART_INF_F;
    g_energy[gt] = e;
}

// ---------------------------------------------------------------------------
// K3a: softmax over T per b. 64 blocks x 256 threads; 8 energies per thread
// held in registers across passes. Writes normalized probs to g_prob AND the
// attention-weights output slice.
// ---------------------------------------------------------------------------
__global__ __launch_bounds__(256) void k_softmax(float* __restrict__ out) {
    const int b = blockIdx.x;
    const int tid = threadIdx.x;
    __shared__ float s_red[8];

    float4 e0 = reinterpret_cast<const float4*>(g_energy + b * T_)[tid * 2];
    float4 e1 = reinterpret_cast<const float4*>(g_energy + b * T_)[tid * 2 + 1];

    float lmax = fmaxf(fmaxf(fmaxf(e0.x, e0.y), fmaxf(e0.z, e0.w)),
                       fmaxf(fmaxf(e1.x, e1.y), fmaxf(e1.z, e1.w)));
#pragma unroll
    for (int off = 16; off; off >>= 1)
        lmax = fmaxf(lmax, __shfl_xor_sync(0xffffffffu, lmax, off));
    if ((tid & 31) == 0) s_red[tid >> 5] = lmax;
    __syncthreads();
    float bmax = s_red[0];
#pragma unroll
    for (int i = 1; i < 8; i++) bmax = fmaxf(bmax, s_red[i]);
    __syncthreads();

    float4 p0 = make_float4(__expf(e0.x - bmax), __expf(e0.y - bmax),
                            __expf(e0.z - bmax), __expf(e0.w - bmax));
    float4 p1 = make_float4(__expf(e1.x - bmax), __expf(e1.y - bmax),
                            __expf(e1.z - bmax), __expf(e1.w - bmax));
    float lsum = (p0.x + p0.y) + (p0.z + p0.w) + (p1.x + p1.y) + (p1.z + p1.w);
#pragma unroll
    for (int off = 16; off; off >>= 1)
        lsum += __shfl_xor_sync(0xffffffffu, lsum, off);
    if ((tid & 31) == 0) s_red[tid >> 5] = lsum;
    __syncthreads();
    float bsum = 0.f;
#pragma unroll
    for (int i = 0; i < 8; i++) bsum += s_red[i];
    const float inv = 1.f / bsum;

    p0.x *= inv; p0.y *= inv; p0.z *= inv; p0.w *= inv;
    p1.x *= inv; p1.y *= inv; p1.z *= inv; p1.w *= inv;
    reinterpret_cast<float4*>(g_prob + b * T_)[tid * 2] = p0;
    reinterpret_cast<float4*>(g_prob + b * T_)[tid * 2 + 1] = p1;
    float* ow = out + B_ * EMB_ + b * T_;
    reinterpret_cast<float4*>(ow)[tid * 2] = p0;
    reinterpret_cast<float4*>(ow)[tid * 2 + 1] = p1;
}

// ---------------------------------------------------------------------------
// K3b: context matvec. grid (4, B), 512 threads = 8 t-phases x 64 d (float2).
// Explicit 8-deep load batching for DRAM MLP.
// ---------------------------------------------------------------------------
__global__ __launch_bounds__(512) void k_ctx(const float* __restrict__ mem,
                                             float* __restrict__ out) {
    const int b = blockIdx.y;
    const int dc = blockIdx.x;      // 0..3 -> 128 dims each
    const int tid = threadIdx.x;

    __shared__ float s_p[T_];
    __shared__ float2 s_acc[512];

    reinterpret_cast<float4*>(s_p)[tid] =
        reinterpret_cast<const float4*>(g_prob + b * T_)[tid];
    __syncthreads();

    const int ph = tid >> 6;        // 0..7
    const float2* mp = reinterpret_cast<const float2*>(
        mem + (size_t)b * T_ * EMB_ + dc * 128) + (tid & 63);
    float2 acc = make_float2(0.f, 0.f);
    for (int tb = ph; tb < T_; tb += 64) {
        float2 r[8];
#pragma unroll
        for (int u = 0; u < 8; u++) r[u] = mp[(size_t)(tb + u * 8) * 256];
#pragma unroll
        for (int u = 0; u < 8; u++) {
            float p = s_p[tb + u * 8];
            acc.x += p * r[u].x;
            acc.y += p * r[u].y;
        }
    }
    s_acc[tid] = acc;
    __syncthreads();
    if (tid < 64) {
        float2 tot = make_float2(0.f, 0.f);
#pragma unroll
        for (int k = 0; k < 8; k++) {
            float2 v = s_acc[k * 64 + tid];
            tot.x += v.x;
            tot.y += v.y;
        }
        reinterpret_cast<float2*>(out + b * EMB_ + dc * 128)[tid] = tot;
    }
}

// ---------------------------------------------------------------------------
extern "C" void kernel_launch(void* const* d_in, const int* in_sizes, int n_in,
                              void* d_out, int out_size) {
    const float* query = (const float*)d_in[0];
    const float* pm    = (const float*)d_in[1];
    const float* cat   = (const float*)d_in[2];
    const int*   mask  = (const int*)d_in[3];
    const float* mem   = (const float*)d_in[4];
    const float* Wq    = (const float*)d_in[5];
    const float* cw    = (const float*)d_in[6];
    const float* Wl    = (const float*)d_in[7];
    const float* vw    = (const float*)d_in[8];
    float* out = (float*)d_out;

    k_query<<<512, 256>>>(query, Wq);
    dim3 g2(T_ / TILE_, B_);
    k_energy<<<g2, 128>>>(pm, cat, mask, cw, Wl, vw);
    k_softmax<<<B_, 256>>>(out);
    dim3 g3(4, B_);
    k_ctx<<<g3, 512>>>(mem, out);
}